// round 16
// baseline (speedup 1.0000x reference)
#include <cuda_runtime.h>
#include <cuda_fp16.h>
#include <math.h>

#define NT 256
#define NWARP 8
#define MAX_K 128
#define E_DIM 1024
#define MAX_B 2048
#define MAX_VPAD 100352          // 98 * 1024
#define MAX_REFS (MAX_B * MAX_K)

// ---------------- static scratch (allocation-free) ----------------
__device__ int g_is64;
__device__ unsigned int g_total;
__device__ __align__(16) unsigned int g_count[MAX_VPAD];
__device__ __align__(16) unsigned int g_offset[MAX_VPAD];
__device__ __align__(16) unsigned int g_payload[MAX_REFS];
__device__ __align__(16) unsigned int g_bidx[MAX_REFS];      // (idx << 7) | rank_within_idx
__device__ __align__(16) __half g_ro[MAX_B * E_DIM];
__device__ float g_logits[MAX_B * MAX_K];

// ============ K1: zero counts + i64 detect (tiny, runs first) ============
__global__ __launch_bounds__(NT) void init_kernel(
    const unsigned int* __restrict__ labels_raw, int nzb, int n_slots)
{
    const int bid = blockIdx.x, tid = threadIdx.x;
    if (bid < nzb) {                           // zero 1024 counters per block
        int i = bid * 1024 + tid * 4;
        *reinterpret_cast<uint4*>(&g_count[i]) = make_uint4(0, 0, 0, 0);
    } else {                                   // single detect block
        __shared__ int bad;
        if (tid == 0) { bad = 0; g_total = 0u; }
        __syncthreads();
        for (int i = tid; i < n_slots; i += NT)
            if (labels_raw[2 * i + 1] != 0u) bad = 1;
        __syncthreads();
        if (tid == 0) g_is64 = (bad == 0);
    }
}

// ============ K2: fused ro-normalize (blocks < B) + histogram (blocks >= B) ============
__global__ __launch_bounds__(NT) void prep_hist_kernel(
    const float* __restrict__ recv,
    const void* __restrict__ nns, const void* __restrict__ labels,
    const int* __restrict__ nhn,
    float* __restrict__ out, int B, int out_size, int Kn)
{
    const int bid = blockIdx.x, tid = threadIdx.x;

    if (bid >= B) {
        // ---- histogram role: 256 refs per block ----
        int i = (bid - B) * NT + tid;
        int b = i >> 7, n = i & 127;
        if (b >= B) return;
        int K = (nhn ? *nhn : MAX_K - 1) + 1;
        if (n >= K || n >= Kn) { g_bidx[i] = 0xffffffffu; return; }
        const int is64 = g_is64;
        long long lab = is64 ? reinterpret_cast<const long long*>(labels)[b]
                             : (long long)reinterpret_cast<const int*>(labels)[b];
        long long idx = is64 ? reinterpret_cast<const long long*>(nns)[lab * Kn + n]
                             : (long long)reinterpret_cast<const int*>(nns)[lab * Kn + n];
        unsigned int rank = atomicAdd(&g_count[(int)idx], 1u);
        g_bidx[i] = ((unsigned int)idx << 7) | (rank & 127u);
        return;
    }

    // ---- ro-normalize role ----
    const int lane = tid & 31, warp = tid >> 5;
    __shared__ float s_ro[E_DIM];
    __shared__ float s_ss[NWARP], s_mx[NWARP];
    __shared__ int   s_mi[NWARP];
    __shared__ float s_inv, s_acc;

    const float* rrow = recv + (size_t)bid * E_DIM;
    float ss, mx; int mi;
    {
        int e = tid * 4;
        float4 v = __ldcs(reinterpret_cast<const float4*>(rrow + e));
        *reinterpret_cast<float4*>(s_ro + e) = v;
        ss = v.x * v.x + v.y * v.y + v.z * v.z + v.w * v.w;
        mx = v.x; mi = e;
        if (v.y > mx) { mx = v.y; mi = e + 1; }
        if (v.z > mx) { mx = v.z; mi = e + 2; }
        if (v.w > mx) { mx = v.w; mi = e + 3; }
    }
    #pragma unroll
    for (int off = 16; off > 0; off >>= 1) {
        float oss = __shfl_down_sync(0xffffffffu, ss, off);
        float omx = __shfl_down_sync(0xffffffffu, mx, off);
        int   omi = __shfl_down_sync(0xffffffffu, mi, off);
        ss += oss;
        if (omx > mx || (omx == mx && omi < mi)) { mx = omx; mi = omi; }
    }
    if (lane == 0) { s_ss[warp] = ss; s_mx[warp] = mx; s_mi[warp] = mi; }
    __syncthreads();
    if (tid == 0) {
        float tss = 0.f, tmx = -1e30f; int tmi = 0x7fffffff;
        #pragma unroll
        for (int w = 0; w < NWARP; w++) {
            tss += s_ss[w];
            if (s_mx[w] > tmx || (s_mx[w] == tmx && s_mi[w] < tmi)) { tmx = s_mx[w]; tmi = s_mi[w]; }
        }
        s_inv = rsqrtf(tss);
        s_acc = (tmi == 0) ? 1.0f : 0.0f;
    }
    __syncthreads();
    const float inv = s_inv;
    float4 v = *reinterpret_cast<const float4*>(s_ro + tid * 4);
    __half2 h0 = __floats2half2_rn(v.x * inv, v.y * inv);
    __half2 h1 = __floats2half2_rn(v.z * inv, v.w * inv);
    uint2 u; u.x = *reinterpret_cast<unsigned int*>(&h0); u.y = *reinterpret_cast<unsigned int*>(&h1);
    reinterpret_cast<uint2*>(g_ro + (size_t)bid * E_DIM)[tid] = u;
    if (tid == 0 && out_size >= 2 * B) out[B + bid] = s_acc;
}

// ---------------- K3: offset assignment (block scan + one atomic per block) ----------------
__global__ __launch_bounds__(1024) void scan_atomic_kernel() {
    const int t = threadIdx.x, lane = t & 31, w = t >> 5;
    __shared__ unsigned int s_w[32];
    __shared__ unsigned int s_base;
    const unsigned int gid = blockIdx.x * 1024 + t;
    unsigned int v = g_count[gid];
    unsigned int inc = v;
    #pragma unroll
    for (int d = 1; d < 32; d <<= 1) {
        unsigned int u = __shfl_up_sync(0xffffffffu, inc, d);
        if (lane >= d) inc += u;
    }
    if (lane == 31) s_w[w] = inc;
    __syncthreads();
    if (w == 0) {
        unsigned int x = s_w[lane];
        #pragma unroll
        for (int d = 1; d < 32; d <<= 1) {
            unsigned int u = __shfl_up_sync(0xffffffffu, x, d);
            if (lane >= d) x += u;
        }
        s_w[lane] = x;
    }
    __syncthreads();
    unsigned int base = (w > 0) ? s_w[w - 1] : 0u;
    unsigned int excl = base + inc - v;
    if (t == 1023) s_base = atomicAdd(&g_total, base + inc);
    __syncthreads();
    g_offset[gid] = s_base + excl;
}

// ---------------- K4: scatter (no atomic, 4 refs per thread) ----------------
__global__ void scatter_kernel(int nref4)
{
    int i = blockIdx.x * blockDim.x + threadIdx.x;
    if (i >= nref4) return;
    uint4 v = *reinterpret_cast<const uint4*>(&g_bidx[4 * i]);
    unsigned int o0 = 0, o1 = 0, o2 = 0, o3 = 0;
    if (v.x != 0xffffffffu) o0 = g_offset[v.x >> 7] + (v.x & 127u);
    if (v.y != 0xffffffffu) o1 = g_offset[v.y >> 7] + (v.y & 127u);
    if (v.z != 0xffffffffu) o2 = g_offset[v.z >> 7] + (v.z & 127u);
    if (v.w != 0xffffffffu) o3 = g_offset[v.w >> 7] + (v.w & 127u);
    if (v.x != 0xffffffffu) g_payload[o0] = (unsigned int)(4 * i + 0);
    if (v.y != 0xffffffffu) g_payload[o1] = (unsigned int)(4 * i + 1);
    if (v.z != 0xffffffffu) g_payload[o2] = (unsigned int)(4 * i + 2);
    if (v.w != 0xffffffffu) g_payload[o3] = (unsigned int)(4 * i + 3);
}

// ============ K5: main pass: one warp per neighbor id, emb row in smem, paired refs ============
__global__ __launch_bounds__(NT) void group_kernel(const float* __restrict__ emb, int V)
{
    const int warp = threadIdx.x >> 5;
    const int lane = threadIdx.x & 31;
    const int gw   = blockIdx.x * NWARP + warp;           // neighbor id
    __shared__ __align__(16) float s_emb[NWARP][E_DIM];
    if (gw >= V) return;
    const unsigned int cnt = g_count[gw];
    if (cnt == 0) return;
    const unsigned int off = g_offset[gw];

    // load emb row (4KB) into warp-private smem; evict-first to protect ro in L2
    const float4* er = reinterpret_cast<const float4*>(emb + (size_t)gw * E_DIM);
    float4* se = reinterpret_cast<float4*>(s_emb[warp]);
    #pragma unroll
    for (int j = 0; j < 8; j++) se[lane + 32 * j] = __ldcs(er + lane + 32 * j);
    __syncwarp();

    unsigned int r = 0;
    for (; r + 2 <= cnt; r += 2) {
        const unsigned int p0 = __ldcs(&g_payload[off + r]);
        const unsigned int p1 = __ldcs(&g_payload[off + r + 1]);
        const uint4* rp0 = reinterpret_cast<const uint4*>(g_ro + (size_t)(p0 >> 7) * E_DIM);
        const uint4* rp1 = reinterpret_cast<const uint4*>(g_ro + (size_t)(p1 >> 7) * E_DIM);
        float a00 = 0.f, a01 = 0.f, a02 = 0.f, a03 = 0.f;
        float a10 = 0.f, a11 = 0.f, a12 = 0.f, a13 = 0.f;
        #pragma unroll
        for (int j = 0; j < 4; j++) {
            const int p = lane + 32 * j;
            uint4 q0 = __ldg(rp0 + p);
            uint4 q1 = __ldg(rp1 + p);
            float4 e0 = se[2 * p];
            float4 e1 = se[2 * p + 1];
            float2 f;
            f = __half22float2(*reinterpret_cast<__half2*>(&q0.x));
            a00 = fmaf(e0.x, f.x, a00); a01 = fmaf(e0.y, f.y, a01);
            f = __half22float2(*reinterpret_cast<__half2*>(&q0.y));
            a02 = fmaf(e0.z, f.x, a02); a03 = fmaf(e0.w, f.y, a03);
            f = __half22float2(*reinterpret_cast<__half2*>(&q0.z));
            a00 = fmaf(e1.x, f.x, a00); a01 = fmaf(e1.y, f.y, a01);
            f = __half22float2(*reinterpret_cast<__half2*>(&q0.w));
            a02 = fmaf(e1.z, f.x, a02); a03 = fmaf(e1.w, f.y, a03);
            f = __half22float2(*reinterpret_cast<__half2*>(&q1.x));
            a10 = fmaf(e0.x, f.x, a10); a11 = fmaf(e0.y, f.y, a11);
            f = __half22float2(*reinterpret_cast<__half2*>(&q1.y));
            a12 = fmaf(e0.z, f.x, a12); a13 = fmaf(e0.w, f.y, a13);
            f = __half22float2(*reinterpret_cast<__half2*>(&q1.z));
            a10 = fmaf(e1.x, f.x, a10); a11 = fmaf(e1.y, f.y, a11);
            f = __half22float2(*reinterpret_cast<__half2*>(&q1.w));
            a12 = fmaf(e1.z, f.x, a12); a13 = fmaf(e1.w, f.y, a13);
        }
        float s0 = (a00 + a01) + (a02 + a03);
        float s1 = (a10 + a11) + (a12 + a13);
        #pragma unroll
        for (int o = 16; o > 0; o >>= 1) {
            s0 += __shfl_xor_sync(0xffffffffu, s0, o);
            s1 += __shfl_xor_sync(0xffffffffu, s1, o);
        }
        if (lane == 0) {
            g_logits[(p0 >> 7) * MAX_K + (p0 & 127)] = s0;
            g_logits[(p1 >> 7) * MAX_K + (p1 & 127)] = s1;
        }
    }
    if (r < cnt) {
        const unsigned int p0 = __ldcs(&g_payload[off + r]);
        const uint4* rp0 = reinterpret_cast<const uint4*>(g_ro + (size_t)(p0 >> 7) * E_DIM);
        float a00 = 0.f, a01 = 0.f, a02 = 0.f, a03 = 0.f;
        #pragma unroll
        for (int j = 0; j < 4; j++) {
            const int p = lane + 32 * j;
            uint4 q0 = __ldg(rp0 + p);
            float4 e0 = se[2 * p];
            float4 e1 = se[2 * p + 1];
            float2 f;
            f = __half22float2(*reinterpret_cast<__half2*>(&q0.x));
            a00 = fmaf(e0.x, f.x, a00); a01 = fmaf(e0.y, f.y, a01);
            f = __half22float2(*reinterpret_cast<__half2*>(&q0.y));
            a02 = fmaf(e0.z, f.x, a02); a03 = fmaf(e0.w, f.y, a03);
            f = __half22float2(*reinterpret_cast<__half2*>(&q0.z));
            a00 = fmaf(e1.x, f.x, a00); a01 = fmaf(e1.y, f.y, a01);
            f = __half22float2(*reinterpret_cast<__half2*>(&q0.w));
            a02 = fmaf(e1.z, f.x, a02); a03 = fmaf(e1.w, f.y, a03);
        }
        float s0 = (a00 + a01) + (a02 + a03);
        #pragma unroll
        for (int o = 16; o > 0; o >>= 1)
            s0 += __shfl_xor_sync(0xffffffffu, s0, o);
        if (lane == 0)
            g_logits[(p0 >> 7) * MAX_K + (p0 & 127)] = s0;
    }
}

// ---------------- K6: log-softmax loss, one warp per batch row ----------------
__global__ void softmax_kernel(float* __restrict__ out, const int* __restrict__ nhn, int B)
{
    const int gw = (blockIdx.x * blockDim.x + threadIdx.x) >> 5;
    const int lane = threadIdx.x & 31;
    if (gw >= B) return;
    const int K = (nhn ? *nhn : MAX_K - 1) + 1;
    float v[4]; float m = -1e30f;
    #pragma unroll
    for (int t = 0; t < 4; t++) {
        int n = lane + 32 * t;
        v[t] = (n < K) ? g_logits[gw * MAX_K + n] : -1e30f;
        m = fmaxf(m, v[t]);
    }
    float z0 = __shfl_sync(0xffffffffu, v[0], 0);
    #pragma unroll
    for (int o = 16; o > 0; o >>= 1)
        m = fmaxf(m, __shfl_xor_sync(0xffffffffu, m, o));
    float se = 0.f;
    #pragma unroll
    for (int t = 0; t < 4; t++)
        if (v[t] > -1e29f) se += expf(v[t] - m);
    #pragma unroll
    for (int o = 16; o > 0; o >>= 1)
        se += __shfl_xor_sync(0xffffffffu, se, o);
    if (lane == 0) out[gw] = -(z0 - m - logf(se));
}

// ---------------- fallback: shape-agnostic direct kernel ----------------
__global__ __launch_bounds__(NT) void disc_loss_kernel(
    const float* __restrict__ recv, const float* __restrict__ emb,
    const void* __restrict__ nns_raw, const void* __restrict__ labels_raw,
    const int* __restrict__ nhn_ptr, float* __restrict__ out,
    int B, int E, int Kn, int out_size)
{
    const int b = blockIdx.x, tid = threadIdx.x;
    const int lane = tid & 31, warp = tid >> 5;
    __shared__ float s_ro[E_DIM];
    __shared__ float s_logits[MAX_K];
    __shared__ float s_ss[NWARP], s_mx[NWARP];
    __shared__ int   s_mi[NWARP];
    __shared__ float s_inv, s_acc;
    const float* rrow = recv + (size_t)b * E;
    float ss = 0.f, mx = -1e30f; int mi = 0x7fffffff;
    for (int e = tid * 4; e < E; e += NT * 4) {
        float4 v = *reinterpret_cast<const float4*>(rrow + e);
        *reinterpret_cast<float4*>(s_ro + e) = v;
        ss += v.x * v.x + v.y * v.y + v.z * v.z + v.w * v.w;
        if (v.x > mx) { mx = v.x; mi = e; }
        if (v.y > mx) { mx = v.y; mi = e + 1; }
        if (v.z > mx) { mx = v.z; mi = e + 2; }
        if (v.w > mx) { mx = v.w; mi = e + 3; }
    }
    #pragma unroll
    for (int off = 16; off > 0; off >>= 1) {
        float oss = __shfl_down_sync(0xffffffffu, ss, off);
        float omx = __shfl_down_sync(0xffffffffu, mx, off);
        int   omi = __shfl_down_sync(0xffffffffu, mi, off);
        ss += oss;
        if (omx > mx || (omx == mx && omi < mi)) { mx = omx; mi = omi; }
    }
    if (lane == 0) { s_ss[warp] = ss; s_mx[warp] = mx; s_mi[warp] = mi; }
    __syncthreads();
    if (tid == 0) {
        float tss = 0.f, tmx = -1e30f; int tmi = 0x7fffffff;
        #pragma unroll
        for (int w = 0; w < NWARP; w++) {
            tss += s_ss[w];
            if (s_mx[w] > tmx || (s_mx[w] == tmx && s_mi[w] < tmi)) { tmx = s_mx[w]; tmi = s_mi[w]; }
        }
        s_inv = rsqrtf(tss);
        s_acc = (tmi == 0) ? 1.0f : 0.0f;
    }
    __syncthreads();
    const float inv = s_inv;
    float ro[32];
    #pragma unroll
    for (int j = 0; j < 8; j++) {
        float4 v = *reinterpret_cast<const float4*>(s_ro + lane * 4 + j * 128);
        ro[4 * j + 0] = v.x * inv; ro[4 * j + 1] = v.y * inv;
        ro[4 * j + 2] = v.z * inv; ro[4 * j + 3] = v.w * inv;
    }
    const int is64 = g_is64;
    const int K = (nhn_ptr ? *nhn_ptr : (MAX_K - 1)) + 1;
    long long lab;
    if (is64) lab = reinterpret_cast<const long long*>(labels_raw)[b];
    else      lab = (long long)reinterpret_cast<const int*>(labels_raw)[b];
    const long long* nrow64 = reinterpret_cast<const long long*>(nns_raw) + (size_t)lab * Kn;
    const int*       nrow32 = reinterpret_cast<const int*>(nns_raw)       + (size_t)lab * Kn;
    for (int n = warp; n < K && n < MAX_K; n += NWARP) {
        long long idx = is64 ? __ldg(nrow64 + n) : (long long)__ldg(nrow32 + n);
        const float4* er = reinterpret_cast<const float4*>(emb + (size_t)idx * E);
        float a0 = 0.f, a1 = 0.f, a2 = 0.f, a3 = 0.f;
        #pragma unroll
        for (int j = 0; j < 8; j++) {
            float4 v = __ldg(er + lane + 32 * j);
            a0 += v.x * ro[4 * j + 0]; a1 += v.y * ro[4 * j + 1];
            a2 += v.z * ro[4 * j + 2]; a3 += v.w * ro[4 * j + 3];
        }
        float acc = (a0 + a1) + (a2 + a3);
        #pragma unroll
        for (int off = 16; off > 0; off >>= 1)
            acc += __shfl_xor_sync(0xffffffffu, acc, off);
        if (lane == 0) s_logits[n] = acc;
    }
    __syncthreads();
    if (warp == 0) {
        float v[4]; float m = -1e30f;
        #pragma unroll
        for (int t = 0; t < 4; t++) {
            int n = lane + 32 * t;
            v[t] = (n < K && n < MAX_K) ? s_logits[n] : -1e30f;
            m = fmaxf(m, v[t]);
        }
        #pragma unroll
        for (int off = 16; off > 0; off >>= 1)
            m = fmaxf(m, __shfl_xor_sync(0xffffffffu, m, off));
        float se = 0.f;
        #pragma unroll
        for (int t = 0; t < 4; t++)
            if (v[t] > -1e29f) se += expf(v[t] - m);
        #pragma unroll
        for (int off = 16; off > 0; off >>= 1)
            se += __shfl_xor_sync(0xffffffffu, se, off);
        if (lane == 0) {
            out[b] = -(s_logits[0] - m - logf(se));
            if (out_size >= 2 * B) out[B + b] = s_acc;
        }
    }
}

extern "C" void kernel_launch(void* const* d_in, const int* in_sizes, int n_in,
                              void* d_out, int out_size)
{
    const float* recv   = (const float*)d_in[0];
    const float* emb    = (const float*)d_in[1];
    const void*  nns    = d_in[2];
    const void*  labels = d_in[3];
    const int*   nhn    = (n_in >= 5) ? (const int*)d_in[4] : nullptr;

    int B  = in_sizes[3];
    int E  = in_sizes[0] / B;
    int V  = in_sizes[1] / E;
    int Kn = in_sizes[2] / V;
    float* out = (float*)d_out;

    bool fast = (E == E_DIM) && (V <= MAX_VPAD) && (B <= MAX_B) && (B % 2 == 0);
    if (!fast) {
        init_kernel<<<1, NT>>>((const unsigned int*)labels, 0, B / 2);
        disc_loss_kernel<<<B, NT>>>(recv, emb, nns, labels, nhn, out, B, E, Kn, out_size);
        return;
    }

    const int nchunks  = (V + 1023) / 1024;
    const int npad     = nchunks * 1024;
    const int nzb      = npad / 1024;
    const int nrefslot = B * 128;
    const int nhistblk = nrefslot / NT;

    init_kernel<<<nzb + 1, NT>>>((const unsigned int*)labels, nzb, B / 2);
    prep_hist_kernel<<<B + nhistblk, NT>>>(recv, nns, labels, nhn, out, B, out_size, Kn);
    scan_atomic_kernel<<<nchunks, 1024>>>();
    scatter_kernel<<<(nrefslot / 4 + 255) / 256, 256>>>(nrefslot / 4);
    group_kernel<<<(V + NWARP - 1) / NWARP, NT>>>(emb, V);
    softmax_kernel<<<(B + NWARP - 1) / NWARP, NT>>>(out, nhn, B);
}

// round 17
// speedup vs baseline: 1.9632x; 1.9632x over previous
#include <cuda_runtime.h>
#include <cuda_fp16.h>
#include <math.h>

#define NT 256
#define NWARP 8
#define MAX_K 128
#define E_DIM 1024
#define MAX_B 2048
#define MAX_VPAD 100352          // 98 * 1024
#define MAX_REFS (MAX_B * MAX_K)

// ---------------- static scratch (allocation-free) ----------------
__device__ int g_is64;
__device__ unsigned int g_total;
__device__ __align__(16) unsigned int g_count[MAX_VPAD];
__device__ __align__(16) unsigned int g_offset[MAX_VPAD];
__device__ __align__(16) unsigned int g_payload[MAX_REFS];
__device__ __align__(16) unsigned int g_bidx[MAX_REFS];      // (idx << 7) | rank_within_idx
__device__ __align__(16) __half g_ro[MAX_B * E_DIM];
__device__ float g_logits[MAX_B * MAX_K];

// ============ K1: zero counts + i64 detect (tiny, runs first) ============
__global__ __launch_bounds__(NT) void init_kernel(
    const unsigned int* __restrict__ labels_raw, int nzb, int n_slots)
{
    const int bid = blockIdx.x, tid = threadIdx.x;
    if (bid < nzb) {                           // zero 1024 counters per block
        int i = bid * 1024 + tid * 4;
        *reinterpret_cast<uint4*>(&g_count[i]) = make_uint4(0, 0, 0, 0);
    } else {                                   // single detect block
        __shared__ int bad;
        if (tid == 0) { bad = 0; g_total = 0u; }
        __syncthreads();
        for (int i = tid; i < n_slots; i += NT)
            if (labels_raw[2 * i + 1] != 0u) bad = 1;
        __syncthreads();
        if (tid == 0) g_is64 = (bad == 0);
    }
}

// ============ K2: fused ro-normalize (blocks < B) + histogram (blocks >= B) ============
__global__ __launch_bounds__(NT) void prep_hist_kernel(
    const float* __restrict__ recv,
    const void* __restrict__ nns, const void* __restrict__ labels,
    const int* __restrict__ nhn,
    float* __restrict__ out, int B, int out_size, int Kn)
{
    const int bid = blockIdx.x, tid = threadIdx.x;

    if (bid >= B) {
        // ---- histogram role: 256 refs per block ----
        int i = (bid - B) * NT + tid;
        int b = i >> 7, n = i & 127;
        if (b >= B) return;
        int K = (nhn ? *nhn : MAX_K - 1) + 1;
        if (n >= K || n >= Kn) { g_bidx[i] = 0xffffffffu; return; }
        const int is64 = g_is64;
        long long lab = is64 ? reinterpret_cast<const long long*>(labels)[b]
                             : (long long)reinterpret_cast<const int*>(labels)[b];
        long long idx = is64 ? reinterpret_cast<const long long*>(nns)[lab * Kn + n]
                             : (long long)reinterpret_cast<const int*>(nns)[lab * Kn + n];
        unsigned int rank = atomicAdd(&g_count[(int)idx], 1u);
        g_bidx[i] = ((unsigned int)idx << 7) | (rank & 127u);
        return;
    }

    // ---- ro-normalize role ----
    const int lane = tid & 31, warp = tid >> 5;
    __shared__ float s_ro[E_DIM];
    __shared__ float s_ss[NWARP], s_mx[NWARP];
    __shared__ int   s_mi[NWARP];
    __shared__ float s_inv, s_acc;

    const float* rrow = recv + (size_t)bid * E_DIM;
    float ss, mx; int mi;
    {
        int e = tid * 4;
        float4 v = __ldcs(reinterpret_cast<const float4*>(rrow + e));
        *reinterpret_cast<float4*>(s_ro + e) = v;
        ss = v.x * v.x + v.y * v.y + v.z * v.z + v.w * v.w;
        mx = v.x; mi = e;
        if (v.y > mx) { mx = v.y; mi = e + 1; }
        if (v.z > mx) { mx = v.z; mi = e + 2; }
        if (v.w > mx) { mx = v.w; mi = e + 3; }
    }
    #pragma unroll
    for (int off = 16; off > 0; off >>= 1) {
        float oss = __shfl_down_sync(0xffffffffu, ss, off);
        float omx = __shfl_down_sync(0xffffffffu, mx, off);
        int   omi = __shfl_down_sync(0xffffffffu, mi, off);
        ss += oss;
        if (omx > mx || (omx == mx && omi < mi)) { mx = omx; mi = omi; }
    }
    if (lane == 0) { s_ss[warp] = ss; s_mx[warp] = mx; s_mi[warp] = mi; }
    __syncthreads();
    if (tid == 0) {
        float tss = 0.f, tmx = -1e30f; int tmi = 0x7fffffff;
        #pragma unroll
        for (int w = 0; w < NWARP; w++) {
            tss += s_ss[w];
            if (s_mx[w] > tmx || (s_mx[w] == tmx && s_mi[w] < tmi)) { tmx = s_mx[w]; tmi = s_mi[w]; }
        }
        s_inv = rsqrtf(tss);
        s_acc = (tmi == 0) ? 1.0f : 0.0f;
    }
    __syncthreads();
    const float inv = s_inv;
    float4 v = *reinterpret_cast<const float4*>(s_ro + tid * 4);
    __half2 h0 = __floats2half2_rn(v.x * inv, v.y * inv);
    __half2 h1 = __floats2half2_rn(v.z * inv, v.w * inv);
    uint2 u; u.x = *reinterpret_cast<unsigned int*>(&h0); u.y = *reinterpret_cast<unsigned int*>(&h1);
    reinterpret_cast<uint2*>(g_ro + (size_t)bid * E_DIM)[tid] = u;
    if (tid == 0 && out_size >= 2 * B) out[B + bid] = s_acc;
}

// ---------------- K3: offset assignment (block scan + one atomic per block) ----------------
__global__ __launch_bounds__(1024) void scan_atomic_kernel() {
    const int t = threadIdx.x, lane = t & 31, w = t >> 5;
    __shared__ unsigned int s_w[32];
    __shared__ unsigned int s_base;
    const unsigned int gid = blockIdx.x * 1024 + t;
    unsigned int v = g_count[gid];
    unsigned int inc = v;
    #pragma unroll
    for (int d = 1; d < 32; d <<= 1) {
        unsigned int u = __shfl_up_sync(0xffffffffu, inc, d);
        if (lane >= d) inc += u;
    }
    if (lane == 31) s_w[w] = inc;
    __syncthreads();
    if (w == 0) {
        unsigned int x = s_w[lane];
        #pragma unroll
        for (int d = 1; d < 32; d <<= 1) {
            unsigned int u = __shfl_up_sync(0xffffffffu, x, d);
            if (lane >= d) x += u;
        }
        s_w[lane] = x;
    }
    __syncthreads();
    unsigned int base = (w > 0) ? s_w[w - 1] : 0u;
    unsigned int excl = base + inc - v;
    if (t == 1023) s_base = atomicAdd(&g_total, base + inc);
    __syncthreads();
    g_offset[gid] = s_base + excl;
}

// ---------------- K4: scatter (no atomic, 4 refs per thread) ----------------
__global__ void scatter_kernel(int nref4)
{
    int i = blockIdx.x * blockDim.x + threadIdx.x;
    if (i >= nref4) return;
    uint4 v = *reinterpret_cast<const uint4*>(&g_bidx[4 * i]);
    unsigned int o0 = 0, o1 = 0, o2 = 0, o3 = 0;
    if (v.x != 0xffffffffu) o0 = g_offset[v.x >> 7] + (v.x & 127u);
    if (v.y != 0xffffffffu) o1 = g_offset[v.y >> 7] + (v.y & 127u);
    if (v.z != 0xffffffffu) o2 = g_offset[v.z >> 7] + (v.z & 127u);
    if (v.w != 0xffffffffu) o3 = g_offset[v.w >> 7] + (v.w & 127u);
    if (v.x != 0xffffffffu) g_payload[o0] = (unsigned int)(4 * i + 0);
    if (v.y != 0xffffffffu) g_payload[o1] = (unsigned int)(4 * i + 1);
    if (v.z != 0xffffffffu) g_payload[o2] = (unsigned int)(4 * i + 2);
    if (v.w != 0xffffffffu) g_payload[o3] = (unsigned int)(4 * i + 3);
}

// ============ K5: main pass — one warp per idx; emb row as fp16 in smem (half LDS) ============
__global__ __launch_bounds__(NT) void group_kernel(const float* __restrict__ emb, int V)
{
    const int warp = threadIdx.x >> 5;
    const int lane = threadIdx.x & 31;
    const int gw   = blockIdx.x * NWARP + warp;           // neighbor id
    __shared__ __align__(16) __half s_emb[NWARP][E_DIM];  // 2 KB per warp
    if (gw >= V) return;
    const unsigned int cnt = g_count[gw];
    if (cnt == 0) return;
    const unsigned int off = g_offset[gw];

    // load emb row (4KB fp32) -> fp16 smem (2KB); evict-first to protect ro in L2
    const float4* er = reinterpret_cast<const float4*>(emb + (size_t)gw * E_DIM);
    uint2* se2 = reinterpret_cast<uint2*>(s_emb[warp]);
    #pragma unroll
    for (int j = 0; j < 8; j++) {
        float4 v = __ldcs(er + lane + 32 * j);
        __half2 h0 = __floats2half2_rn(v.x, v.y);
        __half2 h1 = __floats2half2_rn(v.z, v.w);
        uint2 u; u.x = *reinterpret_cast<unsigned int*>(&h0);
                 u.y = *reinterpret_cast<unsigned int*>(&h1);
        se2[lane + 32 * j] = u;
    }
    __syncwarp();
    const uint4* se4 = reinterpret_cast<const uint4*>(s_emb[warp]);

    unsigned int r = 0;
    for (; r + 2 <= cnt; r += 2) {
        const unsigned int p0 = __ldcs(&g_payload[off + r]);
        const unsigned int p1 = __ldcs(&g_payload[off + r + 1]);
        const uint4* rp0 = reinterpret_cast<const uint4*>(g_ro + (size_t)(p0 >> 7) * E_DIM);
        const uint4* rp1 = reinterpret_cast<const uint4*>(g_ro + (size_t)(p1 >> 7) * E_DIM);
        float a00 = 0.f, a01 = 0.f, a02 = 0.f, a03 = 0.f;
        float a10 = 0.f, a11 = 0.f, a12 = 0.f, a13 = 0.f;
        #pragma unroll
        for (int j = 0; j < 4; j++) {
            const int p = lane + 32 * j;                 // uint4 index: elements 8p..8p+7
            uint4 q0 = __ldg(rp0 + p);
            uint4 q1 = __ldg(rp1 + p);
            uint4 e  = se4[p];                           // one LDS.128 covers both refs
            float2 ea = __half22float2(*reinterpret_cast<__half2*>(&e.x));
            float2 eb = __half22float2(*reinterpret_cast<__half2*>(&e.y));
            float2 ec = __half22float2(*reinterpret_cast<__half2*>(&e.z));
            float2 ed = __half22float2(*reinterpret_cast<__half2*>(&e.w));
            float2 f;
            f = __half22float2(*reinterpret_cast<__half2*>(&q0.x));
            a00 = fmaf(ea.x, f.x, a00); a01 = fmaf(ea.y, f.y, a01);
            f = __half22float2(*reinterpret_cast<__half2*>(&q0.y));
            a02 = fmaf(eb.x, f.x, a02); a03 = fmaf(eb.y, f.y, a03);
            f = __half22float2(*reinterpret_cast<__half2*>(&q0.z));
            a00 = fmaf(ec.x, f.x, a00); a01 = fmaf(ec.y, f.y, a01);
            f = __half22float2(*reinterpret_cast<__half2*>(&q0.w));
            a02 = fmaf(ed.x, f.x, a02); a03 = fmaf(ed.y, f.y, a03);
            f = __half22float2(*reinterpret_cast<__half2*>(&q1.x));
            a10 = fmaf(ea.x, f.x, a10); a11 = fmaf(ea.y, f.y, a11);
            f = __half22float2(*reinterpret_cast<__half2*>(&q1.y));
            a12 = fmaf(eb.x, f.x, a12); a13 = fmaf(eb.y, f.y, a13);
            f = __half22float2(*reinterpret_cast<__half2*>(&q1.z));
            a10 = fmaf(ec.x, f.x, a10); a11 = fmaf(ec.y, f.y, a11);
            f = __half22float2(*reinterpret_cast<__half2*>(&q1.w));
            a12 = fmaf(ed.x, f.x, a12); a13 = fmaf(ed.y, f.y, a13);
        }
        float s0 = (a00 + a01) + (a02 + a03);
        float s1 = (a10 + a11) + (a12 + a13);
        #pragma unroll
        for (int o = 16; o > 0; o >>= 1) {
            s0 += __shfl_xor_sync(0xffffffffu, s0, o);
            s1 += __shfl_xor_sync(0xffffffffu, s1, o);
        }
        if (lane == 0) {
            g_logits[(p0 >> 7) * MAX_K + (p0 & 127)] = s0;
            g_logits[(p1 >> 7) * MAX_K + (p1 & 127)] = s1;
        }
    }
    if (r < cnt) {
        const unsigned int p0 = __ldcs(&g_payload[off + r]);
        const uint4* rp0 = reinterpret_cast<const uint4*>(g_ro + (size_t)(p0 >> 7) * E_DIM);
        float a00 = 0.f, a01 = 0.f, a02 = 0.f, a03 = 0.f;
        #pragma unroll
        for (int j = 0; j < 4; j++) {
            const int p = lane + 32 * j;
            uint4 q0 = __ldg(rp0 + p);
            uint4 e  = se4[p];
            float2 ea = __half22float2(*reinterpret_cast<__half2*>(&e.x));
            float2 eb = __half22float2(*reinterpret_cast<__half2*>(&e.y));
            float2 ec = __half22float2(*reinterpret_cast<__half2*>(&e.z));
            float2 ed = __half22float2(*reinterpret_cast<__half2*>(&e.w));
            float2 f;
            f = __half22float2(*reinterpret_cast<__half2*>(&q0.x));
            a00 = fmaf(ea.x, f.x, a00); a01 = fmaf(ea.y, f.y, a01);
            f = __half22float2(*reinterpret_cast<__half2*>(&q0.y));
            a02 = fmaf(eb.x, f.x, a02); a03 = fmaf(eb.y, f.y, a03);
            f = __half22float2(*reinterpret_cast<__half2*>(&q0.z));
            a00 = fmaf(ec.x, f.x, a00); a01 = fmaf(ec.y, f.y, a01);
            f = __half22float2(*reinterpret_cast<__half2*>(&q0.w));
            a02 = fmaf(ed.x, f.x, a02); a03 = fmaf(ed.y, f.y, a03);
        }
        float s0 = (a00 + a01) + (a02 + a03);
        #pragma unroll
        for (int o = 16; o > 0; o >>= 1)
            s0 += __shfl_xor_sync(0xffffffffu, s0, o);
        if (lane == 0)
            g_logits[(p0 >> 7) * MAX_K + (p0 & 127)] = s0;
    }
}

// ---------------- K6: log-softmax loss, one warp per batch row ----------------
__global__ void softmax_kernel(float* __restrict__ out, const int* __restrict__ nhn, int B)
{
    const int gw = (blockIdx.x * blockDim.x + threadIdx.x) >> 5;
    const int lane = threadIdx.x & 31;
    if (gw >= B) return;
    const int K = (nhn ? *nhn : MAX_K - 1) + 1;
    float v[4]; float m = -1e30f;
    #pragma unroll
    for (int t = 0; t < 4; t++) {
        int n = lane + 32 * t;
        v[t] = (n < K) ? g_logits[gw * MAX_K + n] : -1e30f;
        m = fmaxf(m, v[t]);
    }
    float z0 = __shfl_sync(0xffffffffu, v[0], 0);
    #pragma unroll
    for (int o = 16; o > 0; o >>= 1)
        m = fmaxf(m, __shfl_xor_sync(0xffffffffu, m, o));
    float se = 0.f;
    #pragma unroll
    for (int t = 0; t < 4; t++)
        if (v[t] > -1e29f) se += expf(v[t] - m);
    #pragma unroll
    for (int o = 16; o > 0; o >>= 1)
        se += __shfl_xor_sync(0xffffffffu, se, o);
    if (lane == 0) out[gw] = -(z0 - m - logf(se));
}

// ---------------- fallback: shape-agnostic direct kernel ----------------
__global__ __launch_bounds__(NT) void disc_loss_kernel(
    const float* __restrict__ recv, const float* __restrict__ emb,
    const void* __restrict__ nns_raw, const void* __restrict__ labels_raw,
    const int* __restrict__ nhn_ptr, float* __restrict__ out,
    int B, int E, int Kn, int out_size)
{
    const int b = blockIdx.x, tid = threadIdx.x;
    const int lane = tid & 31, warp = tid >> 5;
    __shared__ float s_ro[E_DIM];
    __shared__ float s_logits[MAX_K];
    __shared__ float s_ss[NWARP], s_mx[NWARP];
    __shared__ int   s_mi[NWARP];
    __shared__ float s_inv, s_acc;
    const float* rrow = recv + (size_t)b * E;
    float ss = 0.f, mx = -1e30f; int mi = 0x7fffffff;
    for (int e = tid * 4; e < E; e += NT * 4) {
        float4 v = *reinterpret_cast<const float4*>(rrow + e);
        *reinterpret_cast<float4*>(s_ro + e) = v;
        ss += v.x * v.x + v.y * v.y + v.z * v.z + v.w * v.w;
        if (v.x > mx) { mx = v.x; mi = e; }
        if (v.y > mx) { mx = v.y; mi = e + 1; }
        if (v.z > mx) { mx = v.z; mi = e + 2; }
        if (v.w > mx) { mx = v.w; mi = e + 3; }
    }
    #pragma unroll
    for (int off = 16; off > 0; off >>= 1) {
        float oss = __shfl_down_sync(0xffffffffu, ss, off);
        float omx = __shfl_down_sync(0xffffffffu, mx, off);
        int   omi = __shfl_down_sync(0xffffffffu, mi, off);
        ss += oss;
        if (omx > mx || (omx == mx && omi < mi)) { mx = omx; mi = omi; }
    }
    if (lane == 0) { s_ss[warp] = ss; s_mx[warp] = mx; s_mi[warp] = mi; }
    __syncthreads();
    if (tid == 0) {
        float tss = 0.f, tmx = -1e30f; int tmi = 0x7fffffff;
        #pragma unroll
        for (int w = 0; w < NWARP; w++) {
            tss += s_ss[w];
            if (s_mx[w] > tmx || (s_mx[w] == tmx && s_mi[w] < tmi)) { tmx = s_mx[w]; tmi = s_mi[w]; }
        }
        s_inv = rsqrtf(tss);
        s_acc = (tmi == 0) ? 1.0f : 0.0f;
    }
    __syncthreads();
    const float inv = s_inv;
    float ro[32];
    #pragma unroll
    for (int j = 0; j < 8; j++) {
        float4 v = *reinterpret_cast<const float4*>(s_ro + lane * 4 + j * 128);
        ro[4 * j + 0] = v.x * inv; ro[4 * j + 1] = v.y * inv;
        ro[4 * j + 2] = v.z * inv; ro[4 * j + 3] = v.w * inv;
    }
    const int is64 = g_is64;
    const int K = (nhn_ptr ? *nhn_ptr : (MAX_K - 1)) + 1;
    long long lab;
    if (is64) lab = reinterpret_cast<const long long*>(labels_raw)[b];
    else      lab = (long long)reinterpret_cast<const int*>(labels_raw)[b];
    const long long* nrow64 = reinterpret_cast<const long long*>(nns_raw) + (size_t)lab * Kn;
    const int*       nrow32 = reinterpret_cast<const int*>(nns_raw)       + (size_t)lab * Kn;
    for (int n = warp; n < K && n < MAX_K; n += NWARP) {
        long long idx = is64 ? __ldg(nrow64 + n) : (long long)__ldg(nrow32 + n);
        const float4* er = reinterpret_cast<const float4*>(emb + (size_t)idx * E);
        float a0 = 0.f, a1 = 0.f, a2 = 0.f, a3 = 0.f;
        #pragma unroll
        for (int j = 0; j < 8; j++) {
            float4 v = __ldg(er + lane + 32 * j);
            a0 += v.x * ro[4 * j + 0]; a1 += v.y * ro[4 * j + 1];
            a2 += v.z * ro[4 * j + 2]; a3 += v.w * ro[4 * j + 3];
        }
        float acc = (a0 + a1) + (a2 + a3);
        #pragma unroll
        for (int off = 16; off > 0; off >>= 1)
            acc += __shfl_xor_sync(0xffffffffu, acc, off);
        if (lane == 0) s_logits[n] = acc;
    }
    __syncthreads();
    if (warp == 0) {
        float v[4]; float m = -1e30f;
        #pragma unroll
        for (int t = 0; t < 4; t++) {
            int n = lane + 32 * t;
            v[t] = (n < K && n < MAX_K) ? s_logits[n] : -1e30f;
            m = fmaxf(m, v[t]);
        }
        #pragma unroll
        for (int off = 16; off > 0; off >>= 1)
            m = fmaxf(m, __shfl_xor_sync(0xffffffffu, m, off));
        float se = 0.f;
        #pragma unroll
        for (int t = 0; t < 4; t++)
            if (v[t] > -1e29f) se += expf(v[t] - m);
        #pragma unroll
        for (int off = 16; off > 0; off >>= 1)
            se += __shfl_xor_sync(0xffffffffu, se, off);
        if (lane == 0) {
            out[b] = -(s_logits[0] - m - logf(se));
            if (out_size >= 2 * B) out[B + b] = s_acc;
        }
    }
}

extern "C" void kernel_launch(void* const* d_in, const int* in_sizes, int n_in,
                              void* d_out, int out_size)
{
    const float* recv   = (const float*)d_in[0];
    const float* emb    = (const float*)d_in[1];
    const void*  nns    = d_in[2];
    const void*  labels = d_in[3];
    const int*   nhn    = (n_in >= 5) ? (const int*)d_in[4] : nullptr;

    int B  = in_sizes[3];
    int E  = in_sizes[0] / B;
    int V  = in_sizes[1] / E;
    int Kn = in_sizes[2] / V;
    float* out = (float*)d_out;

    bool fast = (E == E_DIM) && (V <= MAX_VPAD) && (B <= MAX_B) && (B % 2 == 0);
    if (!fast) {
        init_kernel<<<1, NT>>>((const unsigned int*)labels, 0, B / 2);
        disc_loss_kernel<<<B, NT>>>(recv, emb, nns, labels, nhn, out, B, E, Kn, out_size);
        return;
    }

    const int nchunks  = (V + 1023) / 1024;
    const int npad     = nchunks * 1024;
    const int nzb      = npad / 1024;
    const int nrefslot = B * 128;
    const int nhistblk = nrefslot / NT;

    init_kernel<<<nzb + 1, NT>>>((const unsigned int*)labels, nzb, B / 2);
    prep_hist_kernel<<<B + nhistblk, NT>>>(recv, nns, labels, nhn, out, B, out_size, Kn);
    scan_atomic_kernel<<<nchunks, 1024>>>();
    scatter_kernel<<<(nrefslot / 4 + 255) / 256, 256>>>(nrefslot / 4);
    group_kernel<<<(V + NWARP - 1) / NWARP, NT>>>(emb, V);
    softmax_kernel<<<(B + NWARP - 1) / NWARP, NT>>>(out, nhn, B);
}